// round 1
// baseline (speedup 1.0000x reference)
#include <cuda_runtime.h>

// Problem constants
#define N_LEN   131072
#define B_ROWS  256
#define F_TAPS  16

// Tiling
#define TPB     128
#define EPT     32                    // outputs per thread
#define CHUNK   (TPB*EPT)             // 4096 elements per block per row-pair
#define HALO    32
#define IN_PAIRS  (CHUNK + HALO)      // 4128
#define IN_PAD    ((IN_PAIRS/32)*33)  // 4257 padded pair slots
#define OUT_PAD   ((CHUNK/32)*33)     // 4224
#define SMEM_BYTES ((IN_PAD + OUT_PAD) * 8)

typedef unsigned long long u64;

__device__ float g_dev[33];

__device__ __forceinline__ u64 pack2(float a, float b) {
    u64 r; asm("mov.b64 %0,{%1,%2};" : "=l"(r) : "f"(a), "f"(b)); return r;
}
__device__ __forceinline__ void unpack2(u64 v, float& a, float& b) {
    asm("mov.b64 {%0,%1},%2;" : "=f"(a), "=f"(b) : "l"(v));
}
__device__ __forceinline__ u64 fma2(u64 a, u64 b, u64 c) {
    u64 d; asm("fma.rn.f32x2 %0,%1,%2,%3;" : "=l"(d) : "l"(a), "l"(b), "l"(c)); return d;
}
__device__ __forceinline__ u64 mul2(u64 a, u64 b) {
    u64 d; asm("mul.rn.f32x2 %0,%1,%2;" : "=l"(d) : "l"(a), "l"(b)); return d;
}
__device__ __forceinline__ u64 add2(u64 a, u64 b) {
    u64 d; asm("add.rn.f32x2 %0,%1,%2;" : "=l"(d) : "l"(a), "l"(b)); return d;
}

// pad-33-per-32 swizzle: conflict-free for (32*lane + c) access patterns
__device__ __forceinline__ int sw(int idx) { return (idx >> 5) * 33 + (idx & 31); }

// g = k1 (*) k2, k1 = [1, h0..h15], k2 = [1, h15..h0]
__global__ void compute_g_kernel(const float* __restrict__ h) {
    int m = threadIdx.x;
    if (m < 33) {
        float acc = 0.f;
        for (int j = 0; j <= 16; j++) {
            int mj = m - j;
            if (mj < 0 || mj > 16) continue;
            float a = (j  == 0) ? 1.f : h[j - 1];
            float b = (mj == 0) ? 1.f : h[16 - mj];
            acc = fmaf(a, b, acc);
        }
        g_dev[m] = acc;
    }
}

__global__ __launch_bounds__(TPB) void fir_main(const float* __restrict__ x,
                                                const float* __restrict__ h,
                                                float* __restrict__ y) {
    extern __shared__ u64 smem[];
    u64* sIn  = smem;            // IN_PAD pair slots
    u64* sOut = smem + IN_PAD;   // OUT_PAD pair slots

    const int tid  = threadIdx.x;
    const int pair = blockIdx.y;
    const int c0   = blockIdx.x * CHUNK;
    const float* __restrict__ x0 = x + (size_t)(2 * pair) * N_LEN;
    const float* __restrict__ x1 = x0 + N_LEN;
    float* __restrict__ y0 = y + (size_t)(2 * pair) * N_LEN;
    float* __restrict__ y1 = y0 + N_LEN;

    // broadcast-load combined coefficients, packed (g,g)
    u64 gp[33];
#pragma unroll
    for (int m = 0; m < 33; m++) { float gv = g_dev[m]; gp[m] = pack2(gv, gv); }

    // ---- stage inputs (coalesced float4 loads, pair-interleaved swizzled smem) ----
#pragma unroll
    for (int it = 0; it < 9; it++) {
        int base = tid * 4 + it * (TPB * 4);
        if (base < IN_PAIRS) {
            int p = c0 - HALO + base;      // global position (may be <0 only for blockIdx.x==0)
            float4 a0, a1;
            if (p >= 0) {
                a0 = *reinterpret_cast<const float4*>(x0 + p);
                a1 = *reinterpret_cast<const float4*>(x1 + p);
            } else {
                a0 = make_float4(0.f, 0.f, 0.f, 0.f);
                a1 = make_float4(0.f, 0.f, 0.f, 0.f);
            }
            int ph = sw(base);             // base is 4-aligned -> ph..ph+3 contiguous
            sIn[ph + 0] = pack2(a0.x, a1.x);
            sIn[ph + 1] = pack2(a0.y, a1.y);
            sIn[ph + 2] = pack2(a0.z, a1.z);
            sIn[ph + 3] = pack2(a0.w, a1.w);
        }
    }
    __syncthreads();

    // ---- main compute: 33-tap combined FIR, sliding 32-pair register window ----
    {
        const int lo = tid * EPT;          // local output base (pair index within chunk)
        u64 w[32];                         // w[j] = x-pair at position (i-1-j)
#pragma unroll
        for (int j = 0; j < 32; j++) w[j] = sIn[sw(lo + 31 - j)];

#pragma unroll
        for (int t = 0; t < EPT; t++) {
            u64 xi = sIn[sw(lo + HALO + t)];
            // two independent accumulator chains for ILP
            u64 acc0 = xi;                 // g[0] == 1 exactly
#pragma unroll
            for (int m = 1; m <= 16; m++) acc0 = fma2(gp[m], w[m - 1], acc0);
            u64 acc1 = mul2(gp[17], w[16]);
#pragma unroll
            for (int m = 18; m <= 32; m++) acc1 = fma2(gp[m], w[m - 1], acc1);
            u64 yy = add2(acc0, acc1);
            // shift window (free renaming under full unroll)
#pragma unroll
            for (int j = 31; j > 0; j--) w[j] = w[j - 1];
            w[0] = xi;
            sOut[sw(lo + t)] = yy;
        }
    }

    // ---- exact boundary (outputs i in [0,31]): masked two-stage, warp 0 of chunk 0 ----
    if (blockIdx.x == 0 && tid < 32) {
        __syncwarp(0xffffffffu);           // order after tid 0's fast-path stores
        const int pos = tid;               // output index 0..31
        float ya = 0.f, yb = 0.f;
        if (pos >= F_TAPS) {
            float acc_a = 0.f, acc_b = 0.f;
            for (int q = pos - 16; q <= pos; q++) {
                if (q < F_TAPS) continue;  // v[q] masked to 0
                float coef = (q == pos) ? 1.f : h[16 - pos + q];
                float xa, xb;
                unpack2(sIn[sw(q + HALO)], xa, xb);
                float va = xa, vb = xb;
                for (int j = 0; j < 16; j++) {
                    float ua, ub;
                    unpack2(sIn[sw(q - 1 - j + HALO)], ua, ub);
                    va = fmaf(h[j], ua, va);
                    vb = fmaf(h[j], ub, vb);
                }
                acc_a = fmaf(coef, va, acc_a);
                acc_b = fmaf(coef, vb, acc_b);
            }
            ya = acc_a; yb = acc_b;
        }
        sOut[sw(pos)] = pack2(ya, yb);
    }
    __syncthreads();

    // ---- coalesced writeout ----
#pragma unroll
    for (int it = 0; it < 8; it++) {
        int base = tid * 4 + it * (TPB * 4);
        float o0[4], o1[4];
        int ph = sw(base);
#pragma unroll
        for (int k = 0; k < 4; k++) unpack2(sOut[ph + k], o0[k], o1[k]);
        *reinterpret_cast<float4*>(y0 + c0 + base) = make_float4(o0[0], o0[1], o0[2], o0[3]);
        *reinterpret_cast<float4*>(y1 + c0 + base) = make_float4(o1[0], o1[1], o1[2], o1[3]);
    }
}

extern "C" void kernel_launch(void* const* d_in, const int* in_sizes, int n_in,
                              void* d_out, int out_size) {
    (void)in_sizes; (void)n_in; (void)out_size;
    const float* x = (const float*)d_in[0];
    const float* h = (const float*)d_in[1];
    float* y = (float*)d_out;

    cudaFuncSetAttribute(fir_main, cudaFuncAttributeMaxDynamicSharedMemorySize, SMEM_BYTES);

    compute_g_kernel<<<1, 64>>>(h);
    dim3 grid(N_LEN / CHUNK, B_ROWS / 2, 1);
    fir_main<<<grid, TPB, SMEM_BYTES>>>(x, h, y);
}

// round 2
// speedup vs baseline: 1.3602x; 1.3602x over previous
#include <cuda_runtime.h>

// Problem constants
#define N_LEN   131072
#define B_ROWS  256
#define F_TAPS  16

// Tiling
#define TPB     128
#define EPT     32                    // output pairs per thread
#define CHUNK   (TPB*EPT)             // 4096 positions per block per row-pair
#define HALO    32
#define IN_PAIRS  (CHUNK + HALO)      // 4128
#define IN_PAD    ((IN_PAIRS/32)*33)  // 4257 padded pair slots
#define OUT_PAD   ((CHUNK/32)*33)     // 4224
#define SMEM_BYTES ((IN_PAD + OUT_PAD) * 8)

typedef unsigned long long u64;

__device__ float g_dev[33];

__device__ __forceinline__ u64 pack2(float a, float b) {
    u64 r; asm("mov.b64 %0,{%1,%2};" : "=l"(r) : "f"(a), "f"(b)); return r;
}
__device__ __forceinline__ void unpack2(u64 v, float& a, float& b) {
    asm("mov.b64 {%0,%1},%2;" : "=f"(a), "=f"(b) : "l"(v));
}
__device__ __forceinline__ u64 fma2(u64 a, u64 b, u64 c) {
    u64 d; asm("fma.rn.f32x2 %0,%1,%2,%3;" : "=l"(d) : "l"(a), "l"(b), "l"(c)); return d;
}
__device__ __forceinline__ u64 mul2(u64 a, u64 b) {
    u64 d; asm("mul.rn.f32x2 %0,%1,%2;" : "=l"(d) : "l"(a), "l"(b)); return d;
}
__device__ __forceinline__ u64 add2(u64 a, u64 b) {
    u64 d; asm("add.rn.f32x2 %0,%1,%2;" : "=l"(d) : "l"(a), "l"(b)); return d;
}

// pad-33-per-32 swizzle: stride-32 lane patterns become 2-way instead of 32-way
__device__ __forceinline__ int sw(int idx) { return (idx >> 5) * 33 + (idx & 31); }

// g = k1 (*) k2, k1 = [1, h0..h15], k2 = [1, h15..h0]
__global__ void compute_g_kernel(const float* __restrict__ h) {
    int m = threadIdx.x;
    if (m < 33) {
        float acc = 0.f;
        for (int j = 0; j <= 16; j++) {
            int mj = m - j;
            if (mj < 0 || mj > 16) continue;
            float a = (j  == 0) ? 1.f : h[j - 1];
            float b = (mj == 0) ? 1.f : h[16 - mj];
            acc = fmaf(a, b, acc);
        }
        g_dev[m] = acc;
    }
}

__global__ void __launch_bounds__(TPB, 1) fir_main(const float* __restrict__ x,
                                                   const float* __restrict__ h,
                                                   float* __restrict__ y) {
    extern __shared__ u64 smem[];
    u64* sIn  = smem;            // IN_PAD pair slots: sIn[k] = pair x[c0 - HALO + k]
    u64* sOut = smem + IN_PAD;   // OUT_PAD pair slots

    const int tid  = threadIdx.x;
    const int pair = blockIdx.y;
    const int c0   = blockIdx.x * CHUNK;
    const float* __restrict__ x0 = x + (size_t)(2 * pair) * N_LEN;
    const float* __restrict__ x1 = x0 + N_LEN;
    float* __restrict__ y0 = y + (size_t)(2 * pair) * N_LEN;
    float* __restrict__ y1 = y0 + N_LEN;

    // combined coefficients, packed (g,g) — must stay register-resident
    u64 gp[33];
#pragma unroll
    for (int m = 0; m < 33; m++) { float gv = g_dev[m]; gp[m] = pack2(gv, gv); }

    // ---- stage inputs: one position per lane -> coalesced LDG.32, near-CF STS.64 ----
#pragma unroll
    for (int it = 0; it < (IN_PAIRS + TPB - 1) / TPB; it++) {
        int base = tid + it * TPB;
        if (base < IN_PAIRS) {
            int p = c0 - HALO + base;     // may be <0 only for blockIdx.x==0
            float a0 = 0.f, a1 = 0.f;
            if (p >= 0) { a0 = x0[p]; a1 = x1[p]; }
            sIn[sw(base)] = pack2(a0, a1);
        }
    }
    __syncthreads();

    // ---- main compute: 33-tap combined FIR, register ring buffer (no shifts) ----
    {
        const int lo = tid * EPT;          // local output base (pair index within chunk)
        // ring r: at iteration t, slot (t+j)&31 holds input pair at local pos lo+t+j
        u64 r[32];
#pragma unroll
        for (int s = 0; s < 32; s++) r[s] = sIn[sw(lo + s)];

#pragma unroll
        for (int t = 0; t < EPT; t++) {
            u64 xi = sIn[sw(lo + 32 + t)];         // x at output position (m=0 tap)
            // y[o] = x[o] + sum_{m=1..32} g[m]*x[o-m]; x[o-m] = r[(t+32-m)&31]
            u64 acc0 = xi;                          // g[0] == 1 exactly
#pragma unroll
            for (int m = 1; m <= 16; m++)
                acc0 = fma2(gp[m], r[(t + 32 - m) & 31], acc0);
            u64 acc1 = mul2(gp[17], r[(t + 15) & 31]);
#pragma unroll
            for (int m = 18; m <= 32; m++)
                acc1 = fma2(gp[m], r[(t + 32 - m) & 31], acc1);
            sOut[sw(lo + t)] = add2(acc0, acc1);
            r[t & 31] = xi;                         // overwrite oldest
        }
    }

    // ---- exact boundary (outputs 0..31): masked two-stage, warp 0 of chunk 0 ----
    if (blockIdx.x == 0 && tid < 32) {
        __syncwarp(0xffffffffu);           // order after warp-0 fast-path stores
        const int pos = tid;
        float ya = 0.f, yb = 0.f;
        if (pos >= F_TAPS) {
            float acc_a = 0.f, acc_b = 0.f;
            for (int q = pos - 16; q <= pos; q++) {
                if (q < F_TAPS) continue;  // v[q] masked to 0
                float coef = (q == pos) ? 1.f : h[16 - pos + q];
                float xa, xb;
                unpack2(sIn[sw(q + HALO)], xa, xb);
                float va = xa, vb = xb;
                for (int j = 0; j < 16; j++) {
                    float ua, ub;
                    unpack2(sIn[sw(q - 1 - j + HALO)], ua, ub);
                    va = fmaf(h[j], ua, va);
                    vb = fmaf(h[j], ub, vb);
                }
                acc_a = fmaf(coef, va, acc_a);
                acc_b = fmaf(coef, vb, acc_b);
            }
            ya = acc_a; yb = acc_b;
        }
        sOut[sw(pos)] = pack2(ya, yb);
    }
    __syncthreads();

    // ---- writeout: one position per lane -> near-CF LDS.64, coalesced STG.32 ----
#pragma unroll
    for (int it = 0; it < CHUNK / TPB; it++) {
        int base = tid + it * TPB;
        float a, b;
        unpack2(sOut[sw(base)], a, b);
        y0[c0 + base] = a;
        y1[c0 + base] = b;
    }
}

extern "C" void kernel_launch(void* const* d_in, const int* in_sizes, int n_in,
                              void* d_out, int out_size) {
    (void)in_sizes; (void)n_in; (void)out_size;
    const float* x = (const float*)d_in[0];
    const float* h = (const float*)d_in[1];
    float* y = (float*)d_out;

    cudaFuncSetAttribute(fir_main, cudaFuncAttributeMaxDynamicSharedMemorySize, SMEM_BYTES);

    compute_g_kernel<<<1, 64>>>(h);
    dim3 grid(N_LEN / CHUNK, B_ROWS / 2, 1);
    fir_main<<<grid, TPB, SMEM_BYTES>>>(x, h, y);
}

// round 3
// speedup vs baseline: 1.7017x; 1.2511x over previous
#include <cuda_runtime.h>

// Problem constants
#define N_LEN   131072
#define B_ROWS  256

// Tiling
#define TPB     128
#define EPT     16                     // output pairs per thread per pass
#define CHUNK   (TPB*EPT)              // 2048 positions per block per row-pair
#define IN_PAIRS  (CHUNK + 32)         // 2080  (x halo: 32)
#define V_PAIRS   (CHUNK + 16)         // 2064  (v halo: 16)
#define PAD16(n)  ((((n) + 15) / 16) * 17)
#define IN_PAD    PAD16(IN_PAIRS)      // 2210
#define V_PAD     PAD16(V_PAIRS)       // 2193

typedef unsigned long long u64;

__device__ __forceinline__ u64 pack2(float a, float b) {
    u64 r; asm("mov.b64 %0,{%1,%2};" : "=l"(r) : "f"(a), "f"(b)); return r;
}
__device__ __forceinline__ void unpack2(u64 v, float& a, float& b) {
    asm("mov.b64 {%0,%1},%2;" : "=f"(a), "=f"(b) : "l"(v));
}
__device__ __forceinline__ u64 fma2(u64 a, u64 b, u64 c) {
    u64 d; asm("fma.rn.f32x2 %0,%1,%2,%3;" : "=l"(d) : "l"(a), "l"(b), "l"(c)); return d;
}
__device__ __forceinline__ u64 mul2(u64 a, u64 b) {
    u64 d; asm("mul.rn.f32x2 %0,%1,%2;" : "=l"(d) : "l"(a), "l"(b)); return d;
}
__device__ __forceinline__ u64 add2(u64 a, u64 b) {
    u64 d; asm("add.rn.f32x2 %0,%1,%2;" : "=l"(d) : "l"(a), "l"(b)); return d;
}

// pad-17-per-16 swizzle: conflict-free for stride-16 u64 lane patterns
__device__ __forceinline__ int sw(int idx) { return (idx >> 4) * 17 + (idx & 15); }

__global__ void __launch_bounds__(TPB, 4) fir2(const float* __restrict__ x,
                                               const float* __restrict__ h,
                                               float* __restrict__ y) {
    __shared__ u64 sIn[IN_PAD];   // sIn[k] = x-pair at global pos (c0 - 32 + k); reused for y out
    __shared__ u64 sV[V_PAD];     // sV[k]  = v-pair at global pos (c0 - 16 + k)

    const int tid  = threadIdx.x;
    const int c0   = blockIdx.x * CHUNK;
    const int pair = blockIdx.y;
    const float* __restrict__ x0 = x + (size_t)(2 * pair) * N_LEN;
    const float* __restrict__ x1 = x0 + N_LEN;
    float* __restrict__ y0 = y + (size_t)(2 * pair) * N_LEN;
    float* __restrict__ y1 = y0 + N_LEN;

    // 16 packed coefficients (h[j],h[j]) — shared by both passes (pass 2 uses h[15-j])
    u64 gph[16];
#pragma unroll
    for (int j = 0; j < 16; j++) { float hv = __ldg(h + j); gph[j] = pack2(hv, hv); }

    // ---- stage x: float4 coalesced loads, pair-packed swizzled smem ----
#pragma unroll
    for (int it = 0; it < 5; it++) {
        int grp = tid + it * TPB;              // float4 group index
        if (grp < IN_PAIRS / 4 + 1 && grp * 4 < IN_PAIRS) {
            int base = grp * 4;
            int p = c0 - 32 + base;            // <0 only for blockIdx.x==0
            float4 a0, a1;
            if (p >= 0) {
                a0 = *reinterpret_cast<const float4*>(x0 + p);
                a1 = *reinterpret_cast<const float4*>(x1 + p);
            } else {
                a0 = make_float4(0.f, 0.f, 0.f, 0.f);
                a1 = make_float4(0.f, 0.f, 0.f, 0.f);
            }
            int ph = sw(base);                 // base 4-aligned -> contiguous slots
            sIn[ph + 0] = pack2(a0.x, a1.x);
            sIn[ph + 1] = pack2(a0.y, a1.y);
            sIn[ph + 2] = pack2(a0.z, a1.z);
            sIn[ph + 3] = pack2(a0.w, a1.w);
        }
    }
    __syncthreads();

    const int lo = tid * EPT;

    // ---- pass 1: v[p] = x[p] + sum_{j=0..15} h[j]*x[p-1-j], masked v[p<16]=0 ----
    {
        u64 r[16];                             // x[q] lives at slot q&15 (lo multiple of 16)
#pragma unroll
        for (int s = 0; s < 16; s++) r[s] = sIn[sw(lo + 16 + s)];   // x[c0+lo-16+s]

#pragma unroll
        for (int t = 0; t < EPT; t++) {
            u64 xi = sIn[sw(lo + 32 + t)];     // x[c0+lo+t]
            u64 acc0 = xi;
#pragma unroll
            for (int j = 0; j < 8; j++)        // taps x[p-1-j] at slot (t-1-j)&15
                acc0 = fma2(gph[j], r[(t + 15 - j) & 15], acc0);
            u64 acc1 = mul2(gph[8], r[(t + 7) & 15]);
#pragma unroll
            for (int j = 9; j < 16; j++)
                acc1 = fma2(gph[j], r[(t + 15 - j) & 15], acc1);
            u64 v = add2(acc0, acc1);
            if (c0 + lo + t < 16) v = 0ULL;    // v mask (block 0, thread 0 only)
            sV[sw(lo + 16 + t)] = v;
            r[t & 15] = xi;
        }
    }

    // ---- pass-1 halo: v at global pos (c0-16+tid) for tid<16 ----
    if (tid < 16) {
        int gp = c0 - 16 + tid;                // x[q] -> sIn idx q-c0+32
        u64 v = 0ULL;
        if (gp >= 16) {
            u64 xi = sIn[sw(16 + tid)];
            u64 a0 = xi;
#pragma unroll
            for (int j = 0; j < 8; j++)  a0 = fma2(gph[j], sIn[sw(15 + tid - j)], a0);
            u64 a1 = mul2(gph[8], sIn[sw(7 + tid)]);
#pragma unroll
            for (int j = 9; j < 16; j++) a1 = fma2(gph[j], sIn[sw(15 + tid - j)], a1);
            v = add2(a0, a1);
        }
        sV[sw(tid)] = v;
    }
    __syncthreads();

    // ---- pass 2: y[p] = v[p] + sum_{j} h[15-j]*v[p-1-j], masked y[p<16]=0 ----
    // result written into sIn (x data dead now) for coalesced writeout
    {
        u64 r[16];                             // v[q] at slot q&15
#pragma unroll
        for (int s = 0; s < 16; s++) r[s] = sV[sw(lo + s)];          // v[c0+lo-16+s]

#pragma unroll
        for (int t = 0; t < EPT; t++) {
            u64 vi = sV[sw(lo + 16 + t)];      // v[c0+lo+t]
            u64 acc0 = vi;
#pragma unroll
            for (int j = 0; j < 8; j++)        // hr[j] = h[15-j]
                acc0 = fma2(gph[15 - j], r[(t + 15 - j) & 15], acc0);
            u64 acc1 = mul2(gph[7], r[(t + 7) & 15]);
#pragma unroll
            for (int j = 9; j < 16; j++)
                acc1 = fma2(gph[15 - j], r[(t + 15 - j) & 15], acc1);
            u64 yv = add2(acc0, acc1);
            if (c0 + lo + t < 16) yv = 0ULL;   // y mask
            sIn[sw(lo + t)] = yv;
            r[t & 15] = vi;
        }
    }
    __syncthreads();

    // ---- writeout: float4 coalesced stores ----
#pragma unroll
    for (int it = 0; it < 4; it++) {
        int base = (tid + it * TPB) * 4;
        int ph = sw(base);
        float a[4], b[4];
#pragma unroll
        for (int k = 0; k < 4; k++) unpack2(sIn[ph + k], a[k], b[k]);
        *reinterpret_cast<float4*>(y0 + c0 + base) = make_float4(a[0], a[1], a[2], a[3]);
        *reinterpret_cast<float4*>(y1 + c0 + base) = make_float4(b[0], b[1], b[2], b[3]);
    }
}

extern "C" void kernel_launch(void* const* d_in, const int* in_sizes, int n_in,
                              void* d_out, int out_size) {
    (void)in_sizes; (void)n_in; (void)out_size;
    const float* x = (const float*)d_in[0];
    const float* h = (const float*)d_in[1];
    float* y = (float*)d_out;

    dim3 grid(N_LEN / CHUNK, B_ROWS / 2, 1);
    fir2<<<grid, TPB>>>(x, h, y);
}

// round 6
// speedup vs baseline: 1.8456x; 1.0846x over previous
#include <cuda_runtime.h>

// Problem constants
#define N_LEN   131072
#define B_ROWS  256

// Tiling
#define TPB     128
#define EPT     16                     // output pairs per thread per pass
#define CHUNK   (TPB*EPT)              // 2048 positions per block per row-pair
#define IN_PAIRS  (CHUNK + 32)         // 2080  (x halo: 32)
#define V_PAIRS   (CHUNK + 16)         // 2064  (v halo: 16)
#define PAD16(n)  ((((n) + 15) / 16) * 17)
#define IN_PAD    PAD16(IN_PAIRS)      // 2210
#define V_PAD     PAD16(V_PAIRS)       // 2193

typedef unsigned long long u64;

__device__ __forceinline__ u64 pack2(float a, float b) {
    u64 r; asm("mov.b64 %0,{%1,%2};" : "=l"(r) : "f"(a), "f"(b)); return r;
}
__device__ __forceinline__ void unpack2(u64 v, float& a, float& b) {
    asm("mov.b64 {%0,%1},%2;" : "=f"(a), "=f"(b) : "l"(v));
}
__device__ __forceinline__ u64 fma2(u64 a, u64 b, u64 c) {
    u64 d; asm("fma.rn.f32x2 %0,%1,%2,%3;" : "=l"(d) : "l"(a), "l"(b), "l"(c)); return d;
}
__device__ __forceinline__ u64 mul2(u64 a, u64 b) {
    u64 d; asm("mul.rn.f32x2 %0,%1,%2;" : "=l"(d) : "l"(a), "l"(b)); return d;
}
__device__ __forceinline__ u64 add2(u64 a, u64 b) {
    u64 d; asm("add.rn.f32x2 %0,%1,%2;" : "=l"(d) : "l"(a), "l"(b)); return d;
}

// pad-17-per-16 swizzle: conflict-free for stride-16 u64 lane patterns
__device__ __forceinline__ int sw(int idx) { return (idx >> 4) * 17 + (idx & 15); }

__global__ void __launch_bounds__(TPB, 4) fir2(const float* __restrict__ x,
                                               const float* __restrict__ h,
                                               float* __restrict__ y) {
    __shared__ u64 sIn[IN_PAD];   // sIn[k] = x-pair at pos (c0 - 32 + k); reused for y staging
    __shared__ u64 sV[V_PAD];     // sV[k]  = v-pair at pos (c0 - 16 + k)

    const int tid  = threadIdx.x;
    const int c0   = blockIdx.x * CHUNK;
    const int pair = blockIdx.y;
    const float* __restrict__ x0 = x + (size_t)(2 * pair) * N_LEN;
    const float* __restrict__ x1 = x0 + N_LEN;
    float* __restrict__ y0 = y + (size_t)(2 * pair) * N_LEN;
    float* __restrict__ y1 = y0 + N_LEN;

    // 16 packed coefficients (h[j],h[j]) — pass 2 uses the reversed indexing h[15-j]
    u64 gph[16];
#pragma unroll
    for (int j = 0; j < 16; j++) { float hv = __ldg(h + j); gph[j] = pack2(hv, hv); }

    // ---- stage x: float4 coalesced loads, pair-packed swizzled smem ----
#pragma unroll
    for (int it = 0; it < 5; it++) {
        int grp = tid + it * TPB;              // float4 group index (520 groups)
        if (grp * 4 < IN_PAIRS) {
            int base = grp * 4;
            int p = c0 - 32 + base;            // <0 only for blockIdx.x==0
            float4 a0, a1;
            if (p >= 0) {
                a0 = *reinterpret_cast<const float4*>(x0 + p);
                a1 = *reinterpret_cast<const float4*>(x1 + p);
            } else {
                a0 = make_float4(0.f, 0.f, 0.f, 0.f);
                a1 = make_float4(0.f, 0.f, 0.f, 0.f);
            }
            int ph = sw(base);                 // base 4-aligned -> contiguous slots
            sIn[ph + 0] = pack2(a0.x, a1.x);
            sIn[ph + 1] = pack2(a0.y, a1.y);
            sIn[ph + 2] = pack2(a0.z, a1.z);
            sIn[ph + 3] = pack2(a0.w, a1.w);
        }
    }
    __syncthreads();

    const int lo = tid * EPT;
    const bool kill = (blockIdx.x == 0) && (tid == 0);   // positions 0..15: v and y masked to 0

    // ---- pass 1: v[p] = x[p] + sum_{j=0..15} h[j]*x[p-1-j]; results kept in regs ----
    u64 vbuf[16];
    {
        u64 r[16];                             // x ring: x[q] at slot q&15
#pragma unroll
        for (int s = 0; s < 16; s++) r[s] = sIn[sw(lo + 16 + s)];   // x[c0+lo-16+s]

#pragma unroll
        for (int t = 0; t < EPT; t++) {
            u64 xi = sIn[sw(lo + 32 + t)];     // x[c0+lo+t]
            u64 acc0 = xi;
#pragma unroll
            for (int j = 0; j < 8; j++)
                acc0 = fma2(gph[j], r[(t + 15 - j) & 15], acc0);
            u64 acc1 = mul2(gph[8], r[(t + 7) & 15]);
#pragma unroll
            for (int j = 9; j < 16; j++)
                acc1 = fma2(gph[j], r[(t + 15 - j) & 15], acc1);
            vbuf[t] = add2(acc0, acc1);
            r[t & 15] = xi;
        }
    }
    if (kill) {                                // v[0..15] = 0 (hoisted mask)
#pragma unroll
        for (int t = 0; t < EPT; t++) vbuf[t] = 0ULL;
    }
    // publish v for the next thread's halo
#pragma unroll
    for (int t = 0; t < EPT; t++) sV[sw(lo + 16 + t)] = vbuf[t];

    // ---- pass-1 halo: v at pos (c0-16+tid) for tid<16, recomputed from x ----
    if (tid < 16) {
        int gp = c0 - 16 + tid;
        u64 v = 0ULL;
        if (gp >= 16) {
            u64 xi = sIn[sw(16 + tid)];
            u64 a0 = xi;
#pragma unroll
            for (int j = 0; j < 8; j++)  a0 = fma2(gph[j], sIn[sw(15 + tid - j)], a0);
            u64 a1 = mul2(gph[8], sIn[sw(7 + tid)]);
#pragma unroll
            for (int j = 9; j < 16; j++) a1 = fma2(gph[j], sIn[sw(15 + tid - j)], a1);
            v = add2(a0, a1);
        }
        sV[sw(tid)] = v;
    }
    __syncthreads();

    // ---- pass 2: y[p] = v[p] + sum_{j} h[15-j]*v[p-1-j]; pure register window ----
    {
        u64 hv[16];                            // halo: v[c0+lo-16+s]
#pragma unroll
        for (int s = 0; s < 16; s++) hv[s] = sV[sw(lo + s)];

#pragma unroll
        for (int t = 0; t < EPT; t++) {
            u64 acc0 = vbuf[t];
#pragma unroll
            for (int j = 0; j < 8; j++) {      // tap v[lo+t-1-j]
                int k = t - 1 - j;
                u64 tap = (k >= 0) ? vbuf[k] : hv[16 + k];
                acc0 = fma2(gph[15 - j], tap, acc0);
            }
            u64 tap8;
            { int k = t - 9; tap8 = (k >= 0) ? vbuf[k] : hv[16 + k]; }
            u64 acc1 = mul2(gph[7], tap8);
#pragma unroll
            for (int j = 9; j < 16; j++) {
                int k = t - 1 - j;
                u64 tap = (k >= 0) ? vbuf[k] : hv[16 + k];
                acc1 = fma2(gph[15 - j], tap, acc1);
            }
            sIn[sw(lo + t)] = add2(acc0, acc1);   // y staged into sIn (x dead now)
        }
    }
    if (kill) {                                // y[0..15] = 0 (hoisted mask)
#pragma unroll
        for (int t = 0; t < EPT; t++) sIn[sw(t)] = 0ULL;
    }
    __syncthreads();

    // ---- writeout: float4 coalesced stores ----
#pragma unroll
    for (int it = 0; it < 4; it++) {
        int base = (tid + it * TPB) * 4;
        int ph = sw(base);
        float a[4], b[4];
#pragma unroll
        for (int k = 0; k < 4; k++) unpack2(sIn[ph + k], a[k], b[k]);
        *reinterpret_cast<float4*>(y0 + c0 + base) = make_float4(a[0], a[1], a[2], a[3]);
        *reinterpret_cast<float4*>(y1 + c0 + base) = make_float4(b[0], b[1], b[2], b[3]);
    }
}

extern "C" void kernel_launch(void* const* d_in, const int* in_sizes, int n_in,
                              void* d_out, int out_size) {
    (void)in_sizes; (void)n_in; (void)out_size;
    const float* x = (const float*)d_in[0];
    const float* h = (const float*)d_in[1];
    float* y = (float*)d_out;

    dim3 grid(N_LEN / CHUNK, B_ROWS / 2, 1);
    fir2<<<grid, TPB>>>(x, h, y);
}